// round 16
// baseline (speedup 1.0000x reference)
#include <cuda_runtime.h>
#include <cuda_bf16.h>
#include <cstdint>

#define BATCH  64
#define NANCH  8400
#define MAXOUT 100
#define TPB    512
#define KPT    17            // 512*17 = 8704 >= 8400
#define DT     256           // decode threads per CTA
#define DAANCH 64            // anchors per decode tile (4 threads/anchor)
#define NTILES (BATCH * NANCH / DAANCH)   // 8400 tiles
#define DGRID  444           // 148 SMs * 3 CTAs (persistent)
#define TILEF4 (DAANCH * 37) // padded float4 slots per tile buffer

#define NBUCK  4096
#define BBASE  0xBE80        // bucket = clamp((key>>16) - BBASE, 0, 4095)
#define CAP    384           // max candidates per tier
#define SORTN  512           // sort width (1 elem/thread, zero-padded)
#define TARGET 288           // tier size target
#define NWRD   12            // mask words per row (ceil(CAP/32))

typedef unsigned long long ull;

// ---------------------------------------------------------------------------
// Scratch
// ---------------------------------------------------------------------------
__device__ float4   g_boxes[BATCH * NANCH];
__device__ unsigned g_keys [BATCH * NANCH];   // monotonic score keys (0 = invalid)
__device__ int      g_labels[BATCH * NANCH];

__device__ __forceinline__ void cp_async16(uint32_t dst_smem, const void* src)
{
    asm volatile("cp.async.cg.shared.global [%0], [%1], 16;"
                 :: "r"(dst_smem), "l"(src) : "memory");
}

// ---------------------------------------------------------------------------
// Kernel 1: decode — persistent CTAs, 2-deep cp.async pipeline over
// 64-anchor tiles. Compute body identical to the proven kernel.
// ---------------------------------------------------------------------------
__global__ void __launch_bounds__(DT) decode_kernel(const float* __restrict__ preds,
                                                    const float* __restrict__ anchors)
{
    extern __shared__ float4 sbuf[];          // 2 * 64 * 37 float4 = 75776 B
    const int t = threadIdx.x;

    const float4* __restrict__ pbase = reinterpret_cast<const float4*>(preds);
    const uint32_t sb = (uint32_t)__cvta_generic_to_shared(sbuf);

    const int an = t >> 2;
    const int h  = t & 3;

    // stage-address pattern (same for every tile): slot (a,j) for 9 chunks
    int a0 = t / 36;
    int j0 = t - a0 * 36;

    // ---- prologue: issue load for first tile into buffer 0 ----
    {
        const float4* base = pbase + (size_t)blockIdx.x * DAANCH * 36;
        int a = a0, j = j0;
#pragma unroll
        for (int u = 0; u < 9; ++u) {
            cp_async16(sb + (a * 37 + j) * 16, base + t + u * DT);
            a += 7; j += 4;                    // += 256 = 7*36 + 4
            if (j >= 36) { j -= 36; ++a; }
        }
        asm volatile("cp.async.commit_group;" ::: "memory");
    }

    int iter = 0;
    for (int tile = blockIdx.x; tile < NTILES; tile += DGRID, ++iter) {
        const int bufc = iter & 1;
        const int nxt  = tile + DGRID;
        const bool more = (nxt < NTILES);

        // ---- issue next tile's loads into the other buffer ----
        if (more) {
            const float4* base = pbase + (size_t)nxt * DAANCH * 36;
            const uint32_t dst = sb + (uint32_t)((bufc ^ 1) * TILEF4) * 16;
            int a = a0, j = j0;
#pragma unroll
            for (int u = 0; u < 9; ++u) {
                cp_async16(dst + (a * 37 + j) * 16, base + t + u * DT);
                a += 7; j += 4;
                if (j >= 36) { j -= 36; ++a; }
            }
            asm volatile("cp.async.commit_group;" ::: "memory");
            asm volatile("cp.async.wait_group 1;" ::: "memory");
        } else {
            asm volatile("cp.async.wait_group 0;" ::: "memory");
        }
        __syncthreads();

        const float4* mine = sbuf + bufc * TILEF4 + an * 37;

        // ---- DFL: side h (16 bins) ----
        float d;
        {
            float v[16];
#pragma unroll
            for (int q = 0; q < 4; ++q) {
                float4 f = mine[h * 4 + q];
                v[q * 4 + 0] = f.x; v[q * 4 + 1] = f.y;
                v[q * 4 + 2] = f.z; v[q * 4 + 3] = f.w;
            }
            float m = v[0];
#pragma unroll
            for (int i = 1; i < 16; ++i) m = fmaxf(m, v[i]);
            float se = 0.f, ws = 0.f;
#pragma unroll
            for (int i = 0; i < 16; ++i) {
                float e = __expf(v[i] - m);
                se += e;
                ws = fmaf(e, (float)i, ws);
            }
            d = ws / se;
        }
        float dpart = __shfl_xor_sync(0xffffffffu, d, 2);

        // ---- classes: block [20h, 20h+20), sequential first-max ----
        float best = -3.402823466e38f;
        int lab = 0;
#pragma unroll
        for (int i = 0; i < 5; ++i) {
            float4 f = mine[16 + h * 5 + i];
            int c = h * 20 + 4 * i;
            if (f.x > best) { best = f.x; lab = c + 0; }
            if (f.y > best) { best = f.y; lab = c + 1; }
            if (f.z > best) { best = f.z; lab = c + 2; }
            if (f.w > best) { best = f.w; lab = c + 3; }
        }

        const int gid = tile * DAANCH + an;
        const int nn  = gid % NANCH;
        float4 av = reinterpret_cast<const float4*>(anchors)[nn];
        float aa = (h & 1) ? av.y : av.x;
        float ab = (h & 1) ? av.w : av.z;
        float hw = ab - aa;
        float c0 = (aa + ab) * 0.5f;
        float bc = (dpart - d) * 0.5f * hw + c0;
        float bh = (dpart + d) * hw;
        float lo = bc - bh * 0.5f;
        float hi = bc + bh * 0.5f;

        float olo = __shfl_xor_sync(0xffffffffu, lo, 1);
        float ohi = __shfl_xor_sync(0xffffffffu, hi, 1);

        {
            float ob = __shfl_xor_sync(0xffffffffu, best, 1);
            int   ol = __shfl_xor_sync(0xffffffffu, lab, 1);
            if (ob > best || (ob == best && ol < lab)) { best = ob; lab = ol; }
            ob = __shfl_xor_sync(0xffffffffu, best, 2);
            ol = __shfl_xor_sync(0xffffffffu, lab, 2);
            if (ob > best || (ob == best && ol < lab)) { best = ob; lab = ol; }
        }

        if (h == 0) {
            float4 box; box.x = lo; box.y = olo; box.z = hi; box.w = ohi;
            g_boxes[gid] = box;
        } else if (h == 1) {
            g_keys[gid] = (best > 0.3f) ? (__float_as_uint(best) + 0x80000000u) : 0u;
        } else if (h == 2) {
            g_labels[gid] = lab;
        }

        __syncthreads();   // all reads of bufc done before iter+1 refills it
    }
}

// ---------------------------------------------------------------------------
// Kernel 2: sort-then-mask greedy NMS (exact) — R11 version VERBATIM
// (proven 48.6us, regs=122, no spills).
// ---------------------------------------------------------------------------
__global__ void __launch_bounds__(TPB, 1) nms_kernel(float* __restrict__ out)
{
    extern __shared__ unsigned char dyn[];
    ull*      skey  = (ull*)dyn;                               // SORTN*8 = 4096
    float4*   sbox  = (float4*)(dyn + 4096);                   // SORTN*16 = 8192
    unsigned* smask = (unsigned*)(dyn + 4096 + 8192);          // CAP*NWRD*4 = 18432
    int*      hist  = (int*)(dyn + 4096 + 8192 + 18432);       // NBUCK*4 = 16384

    __shared__ int      blocksum[NBUCK / 32];
    __shared__ float4   s_wbox[MAXOUT];
    __shared__ float    s_warea[MAXOUT];
    __shared__ int      s_wgid[MAXOUT];
    __shared__ unsigned s_wkey[MAXOUT];
    __shared__ unsigned psup[NWRD];
    __shared__ unsigned ssup[NWRD];
    __shared__ int      s_L, s_cnt, s_n, s_W;

    const int b    = blockIdx.x;
    const int t    = threadIdx.x;
    const int warp = t >> 5;
    const int lane = t & 31;

    const float4*   __restrict__ gb = g_boxes + (size_t)b * NANCH;
    const unsigned* __restrict__ gk = g_keys  + (size_t)b * NANCH;

    // ---- keys-only load + histogram ----
    for (int i = t; i < NBUCK; i += TPB) hist[i] = 0;
    __syncthreads();

    unsigned ky[KPT];
#pragma unroll
    for (int k = 0; k < KPT; ++k) {
        int idx = t + k * TPB;
        unsigned kk = (idx < NANCH) ? gk[idx] : 0u;
        ky[k] = kk;
        if (kk) {
            int bkt = (int)(kk >> 16) - BBASE;
            bkt = max(0, min(NBUCK - 1, bkt));
            atomicAdd(&hist[bkt], 1);
        }
    }
    __syncthreads();
    if (t < NBUCK / 32) {
        int s = 0;
#pragma unroll
        for (int q = 0; q < 32; ++q) s += hist[t * 32 + q];
        blocksum[t] = s;
    }
    if (t == 0) s_W = 0;
    __syncthreads();

    int U = NBUCK;
    int W = 0;

    for (int tier = 0; tier < 40 && W < MAXOUT; ++tier) {
        // ---- (a) tier threshold search (thread 0, whole buckets) ----
        if (t == 0) {
            int bb = U, cum = 0;
            while (bb > 0) {
                if ((bb & 31) == 0) {
                    int blk = (bb >> 5) - 1;
                    int bs = blocksum[blk];
                    if (bs == 0) { bb -= 32; continue; }
                    if (cum + bs <= CAP && cum + bs < TARGET) { cum += bs; bb -= 32; continue; }
                }
                int h = hist[bb - 1];
                if (cum > 0 && cum + h > CAP) break;
                cum += h; --bb;
                if (cum >= TARGET) break;
            }
            s_L = bb; s_cnt = cum; s_n = 0;
        }
        skey[t] = 0ull;
        sbox[t] = make_float4(0.f, 0.f, 0.f, 0.f);
        if (t < NWRD) psup[t] = 0u;
        __syncthreads();

        const int L = s_L;
        if (s_cnt == 0) break;                 // pool exhausted

        // ---- (b) compact tier candidates ----
#pragma unroll
        for (int k = 0; k < KPT; ++k) {
            unsigned kk = ky[k];
            if (!kk) continue;
            int bkt = (int)(kk >> 16) - BBASE;
            bkt = max(0, min(NBUCK - 1, bkt));
            if (bkt >= L && bkt < U) {
                int p = atomicAdd(&s_n, 1);
                if (p < CAP)
                    skey[p] = ((ull)kk << 32) | (unsigned)(NANCH - (t + k * TPB));
                ky[k] = 0u;                    // consumed
            }
        }
        __syncthreads();
        const int scount = min(s_n, CAP);
        const int nw = (scount + 31) >> 5;

        // ---- (c) bitonic sort descending: 1 elem/thread, shfl inner phases ----
        {
            ull v = skey[t];
            for (unsigned kk = 2; kk <= SORTN; kk <<= 1) {
                bool desc = ((t & kk) == 0) || (kk == SORTN);
                for (unsigned j = kk >> 1; j; j >>= 1) {
                    ull o;
                    if (j >= 32) {
                        __syncthreads();
                        skey[t] = v;
                        __syncthreads();
                        o = skey[t ^ j];
                    } else {
                        o = __shfl_xor_sync(0xffffffffu, v, j);
                    }
                    bool takeMax = (((t & j) == 0) == desc);
                    v = takeMax ? (v > o ? v : o) : (v < o ? v : o);
                }
            }
            __syncthreads();
            skey[t] = v;
            __syncthreads();
        }

        // ---- (d) gather boxes for sorted candidates ----
        if (t < scount) {
            int gidx = NANCH - (int)(skey[t] & 0xffffffffu);
            sbox[t] = gb[gidx];
        }
        __syncthreads();

        // ---- (e) pre-suppression vs winners from earlier tiers ----
        if (W > 0 && t < scount) {
            float4 a = sbox[t];
            float ai = (a.z - a.x) * (a.w - a.y);
            bool sup = false;
            for (int w = 0; w < W; ++w) {
                float4 wbx = s_wbox[w];
                float tlx = fmaxf(a.x, wbx.x);
                float tly = fmaxf(a.y, wbx.y);
                float brx = fminf(a.z, wbx.z);
                float bry = fminf(a.w, wbx.w);
                float iw = fmaxf(brx - tlx, 0.f);
                float ih = fmaxf(bry - tly, 0.f);
                float inter = iw * ih;
                float rhs = s_warea[w] + 1e-9f;
                sup = sup || (3.f * inter > rhs + ai);
            }
            if (sup) atomicOr(&psup[t >> 5], 1u << (t & 31));
        }
        __syncthreads();

        // ---- (f) triangular mask: row i bit j (j>i) = "i suppresses j" ----
        if (t < scount) {
            const int i = t;
            float4 bi = sbox[i];
            float ai = (bi.z - bi.x) * (bi.w - bi.y);
            float rhs = ai + 1e-9f;
            for (int wb = i >> 5; wb < nw; ++wb) {
                int j0 = wb << 5;
                unsigned word = 0u;
#pragma unroll 8
                for (int l = 0; l < 32; ++l) {
                    int j = j0 + l;
                    float4 a = sbox[j & (SORTN - 1)];
                    float tlx = fmaxf(a.x, bi.x);
                    float tly = fmaxf(a.y, bi.y);
                    float brx = fminf(a.z, bi.z);
                    float bry = fminf(a.w, bi.w);
                    float iw = fmaxf(brx - tlx, 0.f);
                    float ih = fmaxf(bry - tly, 0.f);
                    float inter = iw * ih;
                    float aj = (a.z - a.x) * (a.w - a.y);
                    bool sup = (3.f * inter > rhs + aj) && (j > i) && (j < scount);
                    word |= (sup ? 1u : 0u) << l;
                }
                smask[i * NWRD + wb] = word;
            }
        }
        __syncthreads();

        // ---- (g) serial greedy emit (warp 0) ----
        if (warp == 0) {
            if (lane < NWRD) ssup[lane] = psup[lane];
            __syncwarp();
            int Wl = W;
            for (int wi = 0; wi < nw && Wl < MAXOUT; ++wi) {
                int lim = scount - (wi << 5);
                unsigned validm = (lim >= 32) ? 0xffffffffu : ((1u << lim) - 1u);
                while (Wl < MAXOUT) {
                    unsigned live = (~ssup[wi]) & validm;
                    if (!live) break;
                    int bpos = __ffs(live) - 1;
                    int i = (wi << 5) + bpos;
                    unsigned v = (lane < nw) ? smask[i * NWRD + lane] : 0u;
                    if (lane == wi) v |= (1u << bpos);
                    if (lane < NWRD) ssup[lane] |= v;
                    if (lane == 0) {
                        ull e = skey[i];
                        s_wgid[Wl] = NANCH - (int)(e & 0xffffffffu);
                        s_wkey[Wl] = (unsigned)(e >> 32);
                        float4 bb = sbox[i];
                        s_wbox[Wl] = bb;
                        s_warea[Wl] = (bb.z - bb.x) * (bb.w - bb.y);
                    }
                    ++Wl;
                    __syncwarp();
                }
            }
            if (lane == 0) s_W = Wl;
        }
        __syncthreads();
        W = s_W;
        U = L;
    }

    __syncthreads();

    // ---- output: boxes | labels | scores ----
    if (t < MAXOUT) {
        bool valid = (t < W);
        float4 bv = make_float4(0.f, 0.f, 0.f, 0.f);
        float  sv = 0.f;
        float  lb = -1.f;
        if (valid) {
            bv = s_wbox[t];
            sv = __uint_as_float(s_wkey[t] - 0x80000000u);
            lb = (float)g_labels[(size_t)b * NANCH + s_wgid[t]];
        }
        reinterpret_cast<float4*>(out)[b * MAXOUT + t] = bv;
        out[BATCH * MAXOUT * 4 + b * MAXOUT + t] = lb;
        out[BATCH * MAXOUT * 5 + b * MAXOUT + t] = sv;
    }
}

// ---------------------------------------------------------------------------
extern "C" void kernel_launch(void* const* d_in, const int* in_sizes, int n_in,
                              void* d_out, int out_size)
{
    const float* preds   = (const float*)d_in[0];
    const float* anchors = (const float*)d_in[1];

    const int dec_smem = 2 * TILEF4 * 16;      // 75776
    const int nms_smem = 4096 + 8192 + CAP * NWRD * 4 + NBUCK * 4;

    static int attr_done = 0;
    if (!attr_done) {
        cudaFuncSetAttribute(decode_kernel,
                             cudaFuncAttributeMaxDynamicSharedMemorySize, dec_smem);
        cudaFuncSetAttribute(nms_kernel,
                             cudaFuncAttributeMaxDynamicSharedMemorySize, nms_smem);
        attr_done = 1;
    }

    decode_kernel<<<DGRID, DT, dec_smem>>>(preds, anchors);
    nms_kernel<<<BATCH, TPB, nms_smem>>>((float*)d_out);
}

// round 17
// speedup vs baseline: 1.0614x; 1.0614x over previous
#include <cuda_runtime.h>
#include <cuda_bf16.h>
#include <cstdint>

#define BATCH  64
#define NANCH  8400
#define MAXOUT 100
#define TPB    512
#define KPT    17            // 512*17 = 8704 >= 8400
#define DT     256           // decode threads per CTA
#define DAANCH 64            // anchors per decode CTA (4 threads/anchor)

#define NBUCK  4096
#define BBASE  0xBE80        // bucket = clamp((key>>16) - BBASE, 0, 4095)
#define CAP    384           // max candidates per tier
#define SORTN  512           // sort width (1 elem/thread, zero-padded)
#define TARGET 288           // tier size target
#define NWRD   12            // mask words per row (ceil(CAP/32))

typedef unsigned long long ull;

// ---------------------------------------------------------------------------
// Scratch
// ---------------------------------------------------------------------------
__device__ float4   g_boxes[BATCH * NANCH];
__device__ unsigned g_keys [BATCH * NANCH];   // monotonic score keys (0 = invalid)
__device__ int      g_labels[BATCH * NANCH];

__device__ __forceinline__ void cp_async16(uint32_t dst_smem, const void* src)
{
    asm volatile("cp.async.cg.shared.global [%0], [%1], 16;"
                 :: "r"(dst_smem), "l"(src) : "memory");
}

// ---------------------------------------------------------------------------
// Kernel 1: decode. cp.async staged, 64 anchors / 256 threads -> 4 CTAs/SM.
// (R15 version, proven.)
// ---------------------------------------------------------------------------
__global__ void __launch_bounds__(DT) decode_kernel(const float* __restrict__ preds,
                                                    const float* __restrict__ anchors)
{
    extern __shared__ float4 sbuf[];          // 64 * 37 float4 = 37888 B
    const int t   = threadIdx.x;
    const int cta = blockIdx.x;

    const float4* __restrict__ base =
        reinterpret_cast<const float4*>(preds) + (size_t)cta * DAANCH * 36;
    const uint32_t sb = (uint32_t)__cvta_generic_to_shared(sbuf);

    // ---- coalesced async stage: 2304 float4, incremental div/mod by 36 ----
    {
        int a = t / 36;
        int j = t - a * 36;
#pragma unroll
        for (int u = 0; u < 9; ++u) {
            cp_async16(sb + (a * 37 + j) * 16, base + t + u * DT);
            a += 7; j += 4;                    // += 256 = 7*36 + 4
            if (j >= 36) { j -= 36; ++a; }
        }
    }
    asm volatile("cp.async.commit_group;" ::: "memory");
    asm volatile("cp.async.wait_group 0;" ::: "memory");
    __syncthreads();

    const int an = t >> 2;
    const int h  = t & 3;
    const float4* mine = sbuf + an * 37;

    float d;
    {
        float v[16];
#pragma unroll
        for (int q = 0; q < 4; ++q) {
            float4 f = mine[h * 4 + q];
            v[q * 4 + 0] = f.x; v[q * 4 + 1] = f.y;
            v[q * 4 + 2] = f.z; v[q * 4 + 3] = f.w;
        }
        float m = v[0];
#pragma unroll
        for (int i = 1; i < 16; ++i) m = fmaxf(m, v[i]);
        float se = 0.f, ws = 0.f;
#pragma unroll
        for (int i = 0; i < 16; ++i) {
            float e = __expf(v[i] - m);
            se += e;
            ws = fmaf(e, (float)i, ws);
        }
        d = ws / se;
    }
    float dpart = __shfl_xor_sync(0xffffffffu, d, 2);

    float best = -3.402823466e38f;
    int lab = 0;
#pragma unroll
    for (int i = 0; i < 5; ++i) {
        float4 f = mine[16 + h * 5 + i];
        int c = h * 20 + 4 * i;
        if (f.x > best) { best = f.x; lab = c + 0; }
        if (f.y > best) { best = f.y; lab = c + 1; }
        if (f.z > best) { best = f.z; lab = c + 2; }
        if (f.w > best) { best = f.w; lab = c + 3; }
    }

    const int gid = cta * DAANCH + an;
    const int nn  = gid % NANCH;
    float4 av = reinterpret_cast<const float4*>(anchors)[nn];
    float aa = (h & 1) ? av.y : av.x;
    float ab = (h & 1) ? av.w : av.z;
    float hw = ab - aa;
    float c0 = (aa + ab) * 0.5f;
    float bc = (dpart - d) * 0.5f * hw + c0;
    float bh = (dpart + d) * hw;
    float lo = bc - bh * 0.5f;
    float hi = bc + bh * 0.5f;

    float olo = __shfl_xor_sync(0xffffffffu, lo, 1);
    float ohi = __shfl_xor_sync(0xffffffffu, hi, 1);

    {
        float ob = __shfl_xor_sync(0xffffffffu, best, 1);
        int   ol = __shfl_xor_sync(0xffffffffu, lab, 1);
        if (ob > best || (ob == best && ol < lab)) { best = ob; lab = ol; }
        ob = __shfl_xor_sync(0xffffffffu, best, 2);
        ol = __shfl_xor_sync(0xffffffffu, lab, 2);
        if (ob > best || (ob == best && ol < lab)) { best = ob; lab = ol; }
    }

    if (h == 0) {
        float4 box; box.x = lo; box.y = olo; box.z = hi; box.w = ohi;
        g_boxes[gid] = box;
    } else if (h == 1) {
        g_keys[gid] = (best > 0.3f) ? (__float_as_uint(best) + 0x80000000u) : 0u;
    } else if (h == 2) {
        g_labels[gid] = lab;
    }
}

// ---------------------------------------------------------------------------
// Kernel 2: sort-then-mask greedy NMS (exact). R11 hot loops verbatim;
// per-tier threshold search replaced by parallel suffix-count lookup.
// ---------------------------------------------------------------------------
__global__ void __launch_bounds__(TPB, 1) nms_kernel(float* __restrict__ out)
{
    extern __shared__ unsigned char dyn[];
    ull*      skey  = (ull*)dyn;                               // SORTN*8 = 4096
    float4*   sbox  = (float4*)(dyn + 4096);                   // SORTN*16 = 8192
    unsigned* smask = (unsigned*)(dyn + 4096 + 8192);          // CAP*NWRD*4 = 18432
    int*      hist  = (int*)(dyn + 4096 + 8192 + 18432);       // NBUCK*4 = 16384
    int*      sufc  = (int*)(dyn + 4096 + 8192 + 18432 + 16384); // NBUCK*4 = 16384

    __shared__ int      blocksum[NBUCK / 32];
    __shared__ int      sblkSuf[NBUCK / 32];
    __shared__ float4   s_wbox[MAXOUT];
    __shared__ float    s_warea[MAXOUT];
    __shared__ int      s_wgid[MAXOUT];
    __shared__ unsigned s_wkey[MAXOUT];
    __shared__ unsigned psup[NWRD];
    __shared__ unsigned ssup[NWRD];
    __shared__ int      s_Lb, s_n, s_W;

    const int b    = blockIdx.x;
    const int t    = threadIdx.x;
    const int warp = t >> 5;
    const int lane = t & 31;

    const float4*   __restrict__ gb = g_boxes + (size_t)b * NANCH;
    const unsigned* __restrict__ gk = g_keys  + (size_t)b * NANCH;

    // ---- keys-only load + histogram ----
    for (int i = t; i < NBUCK; i += TPB) hist[i] = 0;
    __syncthreads();

    unsigned ky[KPT];
#pragma unroll
    for (int k = 0; k < KPT; ++k) {
        int idx = t + k * TPB;
        unsigned kk = (idx < NANCH) ? gk[idx] : 0u;
        ky[k] = kk;
        if (kk) {
            int bkt = (int)(kk >> 16) - BBASE;
            bkt = max(0, min(NBUCK - 1, bkt));
            atomicAdd(&hist[bkt], 1);
        }
    }
    __syncthreads();
    if (t < NBUCK / 32) {
        int s = 0;
#pragma unroll
        for (int q = 0; q < 32; ++q) s += hist[t * 32 + q];
        blocksum[t] = s;
    }
    if (t == 0) s_W = 0;
    __syncthreads();

    // ---- suffix counts: sufc[b] = #keys in buckets >= b (computed once) ----
    if (warp == 0) {
        int b0 = blocksum[lane * 4 + 0], b1 = blocksum[lane * 4 + 1];
        int b2 = blocksum[lane * 4 + 2], b3 = blocksum[lane * 4 + 3];
        int tot = b0 + b1 + b2 + b3;
        int p = tot;
#pragma unroll
        for (int off = 1; off < 32; off <<= 1) {
            int o = __shfl_up_sync(0xffffffffu, p, off);
            if (lane >= off) p += o;
        }
        int total_all = __shfl_sync(0xffffffffu, p, 31);
        int sufAfter = total_all - p;          // keys in blocks > lane's last
        sblkSuf[lane * 4 + 3] = sufAfter;
        sblkSuf[lane * 4 + 2] = sufAfter + b3;
        sblkSuf[lane * 4 + 1] = sufAfter + b3 + b2;
        sblkSuf[lane * 4 + 0] = sufAfter + b3 + b2 + b1;
    }
    __syncthreads();
    if (t < NBUCK / 32) {
        int run = sblkSuf[t];                  // keys in buckets >= (t+1)*32
        for (int q = 31; q >= 0; --q) {
            run += hist[t * 32 + q];
            sufc[t * 32 + q] = run;
        }
    }
    __syncthreads();

    int U = NBUCK;
    int W = 0;

    for (int tier = 0; tier < 40 && W < MAXOUT; ++tier) {
        // ---- (a) parallel tier threshold via suffix counts ----
        if (t == 0) { s_Lb = -1; s_n = 0; }
        skey[t] = 0ull;
        sbox[t] = make_float4(0.f, 0.f, 0.f, 0.f);
        if (t < NWRD) psup[t] = 0u;
        __syncthreads();

        const int SU = (U == NBUCK) ? 0 : sufc[U];
        for (int bq = t; bq < U; bq += TPB)
            if (sufc[bq] - SU >= TARGET) atomicMax(&s_Lb, bq);
        __syncthreads();

        int L = s_Lb;
        int cnt;
        if (L < 0) { L = 0; cnt = sufc[0] - SU; }
        else {
            cnt = sufc[L] - SU;
            if (cnt > CAP) {                   // rare: first qualifying bucket huge
                int c2 = (L + 1 < NBUCK) ? (sufc[L + 1] - SU) : 0;
                if (c2 > 0) { L = L + 1; cnt = c2; }
            }
        }
        if (cnt == 0) break;                   // pool exhausted

        // ---- (b) compact tier candidates ----
#pragma unroll
        for (int k = 0; k < KPT; ++k) {
            unsigned kk = ky[k];
            if (!kk) continue;
            int bkt = (int)(kk >> 16) - BBASE;
            bkt = max(0, min(NBUCK - 1, bkt));
            if (bkt >= L && bkt < U) {
                int p = atomicAdd(&s_n, 1);
                if (p < CAP)
                    skey[p] = ((ull)kk << 32) | (unsigned)(NANCH - (t + k * TPB));
                ky[k] = 0u;                    // consumed
            }
        }
        __syncthreads();
        const int scount = min(s_n, CAP);
        const int nw = (scount + 31) >> 5;

        // ---- (c) bitonic sort descending: 1 elem/thread, shfl inner phases ----
        {
            ull v = skey[t];
            for (unsigned kk = 2; kk <= SORTN; kk <<= 1) {
                bool desc = ((t & kk) == 0) || (kk == SORTN);
                for (unsigned j = kk >> 1; j; j >>= 1) {
                    ull o;
                    if (j >= 32) {
                        __syncthreads();
                        skey[t] = v;
                        __syncthreads();
                        o = skey[t ^ j];
                    } else {
                        o = __shfl_xor_sync(0xffffffffu, v, j);
                    }
                    bool takeMax = (((t & j) == 0) == desc);
                    v = takeMax ? (v > o ? v : o) : (v < o ? v : o);
                }
            }
            __syncthreads();
            skey[t] = v;
            __syncthreads();
        }

        // ---- (d) gather boxes for sorted candidates ----
        if (t < scount) {
            int gidx = NANCH - (int)(skey[t] & 0xffffffffu);
            sbox[t] = gb[gidx];
        }
        __syncthreads();

        // ---- (e) pre-suppression vs winners from earlier tiers ----
        if (W > 0 && t < scount) {
            float4 a = sbox[t];
            float ai = (a.z - a.x) * (a.w - a.y);
            bool sup = false;
            for (int w = 0; w < W; ++w) {
                float4 wbx = s_wbox[w];
                float tlx = fmaxf(a.x, wbx.x);
                float tly = fmaxf(a.y, wbx.y);
                float brx = fminf(a.z, wbx.z);
                float bry = fminf(a.w, wbx.w);
                float iw = fmaxf(brx - tlx, 0.f);
                float ih = fmaxf(bry - tly, 0.f);
                float inter = iw * ih;
                float rhs = s_warea[w] + 1e-9f;
                sup = sup || (3.f * inter > rhs + ai);
            }
            if (sup) atomicOr(&psup[t >> 5], 1u << (t & 31));
        }
        __syncthreads();

        // ---- (f) triangular mask: row i bit j (j>i) = "i suppresses j" ----
        if (t < scount) {
            const int i = t;
            float4 bi = sbox[i];
            float ai = (bi.z - bi.x) * (bi.w - bi.y);
            float rhs = ai + 1e-9f;
            for (int wb = i >> 5; wb < nw; ++wb) {
                int j0 = wb << 5;
                unsigned word = 0u;
#pragma unroll 8
                for (int l = 0; l < 32; ++l) {
                    int j = j0 + l;
                    float4 a = sbox[j & (SORTN - 1)];
                    float tlx = fmaxf(a.x, bi.x);
                    float tly = fmaxf(a.y, bi.y);
                    float brx = fminf(a.z, bi.z);
                    float bry = fminf(a.w, bi.w);
                    float iw = fmaxf(brx - tlx, 0.f);
                    float ih = fmaxf(bry - tly, 0.f);
                    float inter = iw * ih;
                    float aj = (a.z - a.x) * (a.w - a.y);
                    bool sup = (3.f * inter > rhs + aj) && (j > i) && (j < scount);
                    word |= (sup ? 1u : 0u) << l;
                }
                smask[i * NWRD + wb] = word;
            }
        }
        __syncthreads();

        // ---- (g) serial greedy emit (warp 0) ----
        if (warp == 0) {
            if (lane < NWRD) ssup[lane] = psup[lane];
            __syncwarp();
            int Wl = W;
            for (int wi = 0; wi < nw && Wl < MAXOUT; ++wi) {
                int lim = scount - (wi << 5);
                unsigned validm = (lim >= 32) ? 0xffffffffu : ((1u << lim) - 1u);
                while (Wl < MAXOUT) {
                    unsigned live = (~ssup[wi]) & validm;
                    if (!live) break;
                    int bpos = __ffs(live) - 1;
                    int i = (wi << 5) + bpos;
                    unsigned v = (lane < nw) ? smask[i * NWRD + lane] : 0u;
                    if (lane == wi) v |= (1u << bpos);
                    if (lane < NWRD) ssup[lane] |= v;
                    if (lane == 0) {
                        ull e = skey[i];
                        s_wgid[Wl] = NANCH - (int)(e & 0xffffffffu);
                        s_wkey[Wl] = (unsigned)(e >> 32);
                        float4 bb = sbox[i];
                        s_wbox[Wl] = bb;
                        s_warea[Wl] = (bb.z - bb.x) * (bb.w - bb.y);
                    }
                    ++Wl;
                    __syncwarp();
                }
            }
            if (lane == 0) s_W = Wl;
        }
        __syncthreads();
        W = s_W;
        U = L;
    }

    __syncthreads();

    // ---- output: boxes | labels | scores ----
    if (t < MAXOUT) {
        bool valid = (t < W);
        float4 bv = make_float4(0.f, 0.f, 0.f, 0.f);
        float  sv = 0.f;
        float  lb = -1.f;
        if (valid) {
            bv = s_wbox[t];
            sv = __uint_as_float(s_wkey[t] - 0x80000000u);
            lb = (float)g_labels[(size_t)b * NANCH + s_wgid[t]];
        }
        reinterpret_cast<float4*>(out)[b * MAXOUT + t] = bv;
        out[BATCH * MAXOUT * 4 + b * MAXOUT + t] = lb;
        out[BATCH * MAXOUT * 5 + b * MAXOUT + t] = sv;
    }
}

// ---------------------------------------------------------------------------
extern "C" void kernel_launch(void* const* d_in, const int* in_sizes, int n_in,
                              void* d_out, int out_size)
{
    const float* preds   = (const float*)d_in[0];
    const float* anchors = (const float*)d_in[1];

    const int nms_smem = 4096 + 8192 + CAP * NWRD * 4 + NBUCK * 4 + NBUCK * 4;

    static int attr_done = 0;
    if (!attr_done) {
        cudaFuncSetAttribute(decode_kernel,
                             cudaFuncAttributeMaxDynamicSharedMemorySize, DAANCH * 37 * 16);
        cudaFuncSetAttribute(nms_kernel,
                             cudaFuncAttributeMaxDynamicSharedMemorySize, nms_smem);
        attr_done = 1;
    }

    decode_kernel<<<(BATCH * NANCH) / DAANCH, DT, DAANCH * 37 * 16>>>(preds, anchors);
    nms_kernel<<<BATCH, TPB, nms_smem>>>((float*)d_out);
}